// round 1
// baseline (speedup 1.0000x reference)
#include <cuda_runtime.h>

// Problem constants
#define BATCH   2
#define SEQ     2048
#define DMODEL  1024
#define NHEADS  16
#define HDIM    64
#define SCALE   64.0f   // reference multiplies scores by head_dim

// Scratch for projected Q/K/V ([B*S, DMODEL] row-major == [b,s,h,dh])
__device__ float g_Q[BATCH * SEQ * DMODEL];
__device__ float g_K[BATCH * SEQ * DMODEL];
__device__ float g_V[BATCH * SEQ * DMODEL];

// ---------------------------------------------------------------------------
// Projection GEMM: C[4096,1024] = A[4096,1024] @ W[1024,1024]
// blockIdx.z selects which of (q,Wq,g_Q), (k,Wk,g_K), (v,Wv,g_V).
// 128x128 block tile, BK=16, 256 threads, 8x8 per-thread micro-tile.
// ---------------------------------------------------------------------------
__global__ __launch_bounds__(256) void proj_gemm(
    const float* __restrict__ qi, const float* __restrict__ ki,
    const float* __restrict__ vi,
    const float* __restrict__ Wq, const float* __restrict__ Wk,
    const float* __restrict__ Wv)
{
    constexpr int N = DMODEL, K = DMODEL;
    const float* A;
    const float* W;
    float* C;
    if (blockIdx.z == 0)      { A = qi; W = Wq; C = g_Q; }
    else if (blockIdx.z == 1) { A = ki; W = Wk; C = g_K; }
    else                      { A = vi; W = Wv; C = g_V; }

    __shared__ float As[16][128];   // transposed A tile: As[k][m]
    __shared__ float Bs[16][128];   // Bs[k][n]

    const int tid = threadIdx.x;
    const int m0 = blockIdx.y * 128;
    const int n0 = blockIdx.x * 128;
    const int ty = tid >> 4;        // 0..15
    const int tx = tid & 15;        // 0..15

    float acc[8][8];
#pragma unroll
    for (int i = 0; i < 8; i++)
#pragma unroll
        for (int j = 0; j < 8; j++) acc[i][j] = 0.0f;

    for (int k0 = 0; k0 < K; k0 += 16) {
        // Load A tile (128 rows x 16 cols), 512 float4s total, 2 per thread.
#pragma unroll
        for (int i = 0; i < 2; i++) {
            int t  = tid * 2 + i;          // 0..511
            int ar = t >> 2;               // 0..127
            int ac = (t & 3) * 4;          // 0,4,8,12
            float4 a4 = *(const float4*)&A[(size_t)(m0 + ar) * K + k0 + ac];
            As[ac + 0][ar] = a4.x;
            As[ac + 1][ar] = a4.y;
            As[ac + 2][ar] = a4.z;
            As[ac + 3][ar] = a4.w;
        }
        // Load W tile (16 rows x 128 cols), 512 float4s, 2 per thread.
#pragma unroll
        for (int i = 0; i < 2; i++) {
            int t  = tid * 2 + i;
            int br = t >> 5;               // 0..15
            int bc = (t & 31) * 4;         // 0..124
            *(float4*)&Bs[br][bc] =
                *(const float4*)&W[(size_t)(k0 + br) * N + n0 + bc];
        }
        __syncthreads();

#pragma unroll
        for (int kk = 0; kk < 16; kk++) {
            float rA[8], rB[8];
#pragma unroll
            for (int i = 0; i < 8; i++) rA[i] = As[kk][ty * 8 + i];
#pragma unroll
            for (int j = 0; j < 8; j++) rB[j] = Bs[kk][tx * 8 + j];
#pragma unroll
            for (int i = 0; i < 8; i++)
#pragma unroll
                for (int j = 0; j < 8; j++)
                    acc[i][j] = fmaf(rA[i], rB[j], acc[i][j]);
        }
        __syncthreads();
    }

#pragma unroll
    for (int i = 0; i < 8; i++)
#pragma unroll
        for (int j = 0; j < 8; j += 4) {
            *(float4*)&C[(size_t)(m0 + ty * 8 + i) * N + n0 + tx * 8 + j] =
                make_float4(acc[i][j], acc[i][j + 1], acc[i][j + 2], acc[i][j + 3]);
        }
}

// ---------------------------------------------------------------------------
// Flash-attention (fp32, online softmax). One CTA per (b, h, 64-row Q tile).
// Streams 64-row K/V tiles. 256 threads; 16x16 thread grid with 4x4 micro
// tiles for both QK^T and PV. Dynamic smem: Q,K,V,S tiles [64][65] + stats.
// ---------------------------------------------------------------------------
#define SW 65   // smem row stride (pad to kill bank conflicts)

__global__ __launch_bounds__(256) void attn_kernel(float* __restrict__ out)
{
    extern __shared__ float sm[];
    float* Qs   = sm;                  // [64][SW]
    float* Ks   = sm + 64 * SW;        // [64][SW]
    float* Vs   = sm + 2 * 64 * SW;    // [64][SW]
    float* Ps   = sm + 3 * 64 * SW;    // scores/probs [64][SW]
    float* m_s  = sm + 4 * 64 * SW;    // [64]
    float* l_s  = m_s + 64;            // [64]
    float* al_s = l_s + 64;            // [64]

    const int tid = threadIdx.x;
    const int qt = blockIdx.x, h = blockIdx.y, b = blockIdx.z;
    const int q0 = qt * 64;
    const int hoff = h * HDIM;

    // Load Q tile: 64 rows x 64 cols, 1024 float4s, 4 per thread.
#pragma unroll
    for (int i = 0; i < 4; i++) {
        int t  = tid + i * 256;
        int r  = t >> 4;
        int c4 = (t & 15) * 4;
        float4 v4 = *(const float4*)&g_Q[(size_t)(b * SEQ + q0 + r) * DMODEL + hoff + c4];
        Qs[r * SW + c4 + 0] = v4.x;
        Qs[r * SW + c4 + 1] = v4.y;
        Qs[r * SW + c4 + 2] = v4.z;
        Qs[r * SW + c4 + 3] = v4.w;
    }
    if (tid < 64) { m_s[tid] = -1e30f; l_s[tid] = 0.0f; }

    const int ty = tid >> 4, tx = tid & 15;
    const int r0 = ty * 4, c0 = tx * 4;

    float accO[4][4];
#pragma unroll
    for (int i = 0; i < 4; i++)
#pragma unroll
        for (int j = 0; j < 4; j++) accO[i][j] = 0.0f;

    __syncthreads();

    for (int kt = 0; kt < SEQ / 64; kt++) {
        const int k0 = kt * 64;
        // Load K and V tiles.
#pragma unroll
        for (int i = 0; i < 4; i++) {
            int t  = tid + i * 256;
            int r  = t >> 4;
            int c4 = (t & 15) * 4;
            size_t gidx = (size_t)(b * SEQ + k0 + r) * DMODEL + hoff + c4;
            float4 kk4 = *(const float4*)&g_K[gidx];
            Ks[r * SW + c4 + 0] = kk4.x;
            Ks[r * SW + c4 + 1] = kk4.y;
            Ks[r * SW + c4 + 2] = kk4.z;
            Ks[r * SW + c4 + 3] = kk4.w;
            float4 vv4 = *(const float4*)&g_V[gidx];
            Vs[r * SW + c4 + 0] = vv4.x;
            Vs[r * SW + c4 + 1] = vv4.y;
            Vs[r * SW + c4 + 2] = vv4.z;
            Vs[r * SW + c4 + 3] = vv4.w;
        }
        __syncthreads();

        // S = (Q @ K^T) * SCALE  -> Ps tile
        {
            float accS[4][4];
#pragma unroll
            for (int i = 0; i < 4; i++)
#pragma unroll
                for (int j = 0; j < 4; j++) accS[i][j] = 0.0f;
#pragma unroll
            for (int kk = 0; kk < 64; kk++) {
                float a[4], bb[4];
#pragma unroll
                for (int i = 0; i < 4; i++) a[i] = Qs[(r0 + i) * SW + kk];
#pragma unroll
                for (int j = 0; j < 4; j++) bb[j] = Ks[(c0 + j) * SW + kk];
#pragma unroll
                for (int i = 0; i < 4; i++)
#pragma unroll
                    for (int j = 0; j < 4; j++)
                        accS[i][j] = fmaf(a[i], bb[j], accS[i][j]);
            }
#pragma unroll
            for (int i = 0; i < 4; i++)
#pragma unroll
                for (int j = 0; j < 4; j++)
                    Ps[(r0 + i) * SW + c0 + j] = accS[i][j] * SCALE;
        }
        __syncthreads();

        // Online softmax: warp w owns rows w*8..w*8+7; all 32 lanes per row.
        {
            const int w = tid >> 5, lane = tid & 31;
#pragma unroll
            for (int rr = 0; rr < 8; rr++) {
                int row = w * 8 + rr;
                float s0 = Ps[row * SW + lane];
                float s1 = Ps[row * SW + lane + 32];
                float mx = fmaxf(s0, s1);
#pragma unroll
                for (int off = 16; off > 0; off >>= 1)
                    mx = fmaxf(mx, __shfl_xor_sync(0xffffffffu, mx, off));
                float mo = m_s[row];
                float mn = fmaxf(mo, mx);
                float p0 = __expf(s0 - mn);
                float p1 = __expf(s1 - mn);
                float sum = p0 + p1;
#pragma unroll
                for (int off = 16; off > 0; off >>= 1)
                    sum += __shfl_xor_sync(0xffffffffu, sum, off);
                Ps[row * SW + lane] = p0;
                Ps[row * SW + lane + 32] = p1;
                if (lane == 0) {
                    float al = __expf(mo - mn);
                    al_s[row] = al;
                    l_s[row] = l_s[row] * al + sum;
                    m_s[row] = mn;
                }
            }
        }
        __syncthreads();

        // O = O * alpha(row) + P @ V
        {
            float al[4];
#pragma unroll
            for (int i = 0; i < 4; i++) al[i] = al_s[r0 + i];
#pragma unroll
            for (int i = 0; i < 4; i++)
#pragma unroll
                for (int j = 0; j < 4; j++) accO[i][j] *= al[i];
#pragma unroll
            for (int kk = 0; kk < 64; kk++) {
                float p[4], vv[4];
#pragma unroll
                for (int i = 0; i < 4; i++) p[i] = Ps[(r0 + i) * SW + kk];
#pragma unroll
                for (int j = 0; j < 4; j++) vv[j] = Vs[kk * SW + c0 + j];
#pragma unroll
                for (int i = 0; i < 4; i++)
#pragma unroll
                    for (int j = 0; j < 4; j++)
                        accO[i][j] = fmaf(p[i], vv[j], accO[i][j]);
            }
        }
        __syncthreads();
    }

    // Epilogue: divide by l, scatter to [b, q, h*64 + c]
    float inv[4];
#pragma unroll
    for (int i = 0; i < 4; i++) inv[i] = 1.0f / l_s[r0 + i];
#pragma unroll
    for (int i = 0; i < 4; i++)
#pragma unroll
        for (int j = 0; j < 4; j++)
            out[(size_t)(b * SEQ + q0 + r0 + i) * DMODEL + hoff + c0 + j] =
                accO[i][j] * inv[i];
}

// ---------------------------------------------------------------------------
// kernel_launch
// ---------------------------------------------------------------------------
extern "C" void kernel_launch(void* const* d_in, const int* in_sizes, int n_in,
                              void* d_out, int out_size)
{
    const float* q  = (const float*)d_in[0];
    const float* k  = (const float*)d_in[1];
    const float* v  = (const float*)d_in[2];
    const float* Wq = (const float*)d_in[3];
    const float* Wk = (const float*)d_in[4];
    const float* Wv = (const float*)d_in[5];
    float* out = (float*)d_out;

    // Stage 1: QKV projections (3 GEMMs via grid.z)
    dim3 ggrid(DMODEL / 128, (BATCH * SEQ) / 128, 3);
    proj_gemm<<<ggrid, 256>>>(q, k, v, Wq, Wk, Wv);

    // Stage 2: flash attention
    const int smem_bytes = (4 * 64 * SW + 3 * 64) * (int)sizeof(float);  // 67,328 B
    cudaFuncSetAttribute(attn_kernel,
                         cudaFuncAttributeMaxDynamicSharedMemorySize, smem_bytes);
    dim3 agrid(SEQ / 64, NHEADS, BATCH);
    attn_kernel<<<agrid, 256, smem_bytes>>>(out);
}

// round 3
// speedup vs baseline: 2.3175x; 2.3175x over previous
#include <cuda_runtime.h>
#include <cuda_bf16.h>
#include <cstdint>

// Problem constants
#define BATCH   2
#define SEQ     2048
#define DMODEL  1024
#define NHEADS  16
#define HDIM    64
#define CEXP    92.33248261689366f   // SCALE(=64) * log2(e)

// Scratch: W^T split-bf16, projected Q/K/V split-bf16
__device__ __nv_bfloat16 g_WT_hi[3 * DMODEL * DMODEL];
__device__ __nv_bfloat16 g_WT_lo[3 * DMODEL * DMODEL];
__device__ __nv_bfloat16 g_Qh[BATCH * SEQ * DMODEL];
__device__ __nv_bfloat16 g_Ql[BATCH * SEQ * DMODEL];
__device__ __nv_bfloat16 g_Kh[BATCH * SEQ * DMODEL];
__device__ __nv_bfloat16 g_Kl[BATCH * SEQ * DMODEL];
__device__ __nv_bfloat16 g_Vh[BATCH * SEQ * DMODEL];
__device__ __nv_bfloat16 g_Vl[BATCH * SEQ * DMODEL];

// ===========================================================================
// Helpers (all sm_80-era PTX: valid on plain compute_103 target)
// ===========================================================================
__device__ __forceinline__ uint32_t smem_u32(const void* p) {
    uint32_t a;
    asm("{ .reg .u64 t; cvta.to.shared.u64 t, %1; cvt.u32.u64 %0, t; }" : "=r"(a) : "l"(p));
    return a;
}

__device__ __forceinline__ void ldm_x4(uint32_t addr, uint32_t* r) {
    asm volatile("ldmatrix.sync.aligned.m8n8.x4.shared.b16 {%0,%1,%2,%3}, [%4];"
                 : "=r"(r[0]), "=r"(r[1]), "=r"(r[2]), "=r"(r[3]) : "r"(addr));
}
__device__ __forceinline__ void ldm_x4t(uint32_t addr, uint32_t* r) {
    asm volatile("ldmatrix.sync.aligned.m8n8.x4.trans.shared.b16 {%0,%1,%2,%3}, [%4];"
                 : "=r"(r[0]), "=r"(r[1]), "=r"(r[2]), "=r"(r[3]) : "r"(addr));
}

// D += A * B^T  (m16n8k16, bf16 in, f32 acc)
__device__ __forceinline__ void mma_bf16(float* c, const uint32_t* a, uint32_t b0, uint32_t b1) {
    asm volatile("mma.sync.aligned.m16n8k16.row.col.f32.bf16.bf16.f32 "
                 "{%0,%1,%2,%3}, {%4,%5,%6,%7}, {%8,%9}, {%0,%1,%2,%3};"
                 : "+f"(c[0]), "+f"(c[1]), "+f"(c[2]), "+f"(c[3])
                 : "r"(a[0]), "r"(a[1]), "r"(a[2]), "r"(a[3]), "r"(b0), "r"(b1));
}

// Split two fp32 into packed bf16x2 hi + lo pairs (p0 -> low half, p1 -> high half)
__device__ __forceinline__ void split2(float p0, float p1, uint32_t& hi, uint32_t& lo) {
    asm("cvt.rn.bf16x2.f32 %0, %1, %2;" : "=r"(hi) : "f"(p1), "f"(p0));
    float h0 = __uint_as_float(hi << 16);
    float h1 = __uint_as_float(hi & 0xFFFF0000u);
    float l0 = p0 - h0;
    float l1 = p1 - h1;
    asm("cvt.rn.bf16x2.f32 %0, %1, %2;" : "=r"(lo) : "f"(l1), "f"(l0));
}

__device__ __forceinline__ float ex2(float x) {
    float r;
    asm("ex2.approx.f32 %0, %1;" : "=f"(r) : "f"(x));
    return r;
}

// ===========================================================================
// W transpose + split-bf16 convert:  g_WT[z][n][k] = W_z[k][n]
// ===========================================================================
__global__ void wt_convert(const float* __restrict__ Wq, const float* __restrict__ Wk,
                           const float* __restrict__ Wv)
{
    __shared__ float tile[32][33];
    const float* W = (blockIdx.z == 0) ? Wq : (blockIdx.z == 1) ? Wk : Wv;
    const int tx = threadIdx.x, ty = threadIdx.y;
    const int k0 = blockIdx.y * 32, n0 = blockIdx.x * 32;
#pragma unroll
    for (int i = 0; i < 4; i++)
        tile[ty + i * 8][tx] = W[(size_t)(k0 + ty + i * 8) * DMODEL + n0 + tx];
    __syncthreads();
    const size_t base = (size_t)blockIdx.z * DMODEL * DMODEL;
#pragma unroll
    for (int i = 0; i < 4; i++) {
        const int n = n0 + ty + i * 8;
        const int k = k0 + tx;
        const float v = tile[tx][ty + i * 8];
        __nv_bfloat16 h = __float2bfloat16(v);
        float lo = v - __bfloat162float(h);
        g_WT_hi[base + (size_t)n * DMODEL + k] = h;
        g_WT_lo[base + (size_t)n * DMODEL + k] = __float2bfloat16(lo);
    }
}

// ===========================================================================
// Projection GEMM (mma.sync, split-bf16 3-term):
//   X = A @ W  -> stored as split bf16 (hi/lo).
// CTA 128x128, 8 warps (4m x 2n), warp tile 32x64, BK=32.
// ===========================================================================
#define PAW 40                   // smem row stride (bf16 elems) -> 80 bytes
#define SA_H_B 0
#define SA_L_B 10240
#define SB_H_B 20480
#define SB_L_B 30720
#define PROJ_SMEM 40960

__global__ __launch_bounds__(256, 1) void proj_mma(const float* __restrict__ qi,
                                                   const float* __restrict__ ki,
                                                   const float* __restrict__ vi)
{
    extern __shared__ char smc[];
    const uint32_t sb = smem_u32(smc);
    const int tid = threadIdx.x;
    const int lane = tid & 31;
    const int wid = tid >> 5;
    const int g = lane >> 2, t4 = lane & 3;
    const int wm = wid & 3, wn = wid >> 2;

    const float* A;
    __nv_bfloat16 *Ch, *Cl;
    if (blockIdx.z == 0)      { A = qi; Ch = g_Qh; Cl = g_Ql; }
    else if (blockIdx.z == 1) { A = ki; Ch = g_Kh; Cl = g_Kl; }
    else                      { A = vi; Ch = g_Vh; Cl = g_Vl; }
    const size_t woff = (size_t)blockIdx.z * DMODEL * DMODEL;

    const int m0 = blockIdx.y * 128;
    const int n0 = blockIdx.x * 128;

    float c[2][8][4];
#pragma unroll
    for (int mb = 0; mb < 2; mb++)
#pragma unroll
        for (int j = 0; j < 8; j++)
#pragma unroll
            for (int i = 0; i < 4; i++) c[mb][j][i] = 0.0f;

    // per-lane ldmatrix base byte offsets
    const uint32_t aBase = (uint32_t)(wm * 32 + (lane & 15)) * 80 + (lane >> 4) * 16;
    const uint32_t bBase = (uint32_t)(wn * 64 + (lane & 7) + ((lane >> 4) << 3)) * 80
                           + ((lane >> 3) & 1) * 16;

    const int lr = tid >> 1, lq = tid & 1;   // load row / half

    for (int kb = 0; kb < 32; kb++) {
        // ---- load A fp32 128x32, split on the fly ----
        {
            const float4* Ap = (const float4*)(A + (size_t)(m0 + lr) * DMODEL + kb * 32 + lq * 16);
            uint32_t hb[8], lb[8];
#pragma unroll
            for (int i = 0; i < 4; i++) {
                float4 a4 = Ap[i];
                split2(a4.x, a4.y, hb[2 * i], lb[2 * i]);
                split2(a4.z, a4.w, hb[2 * i + 1], lb[2 * i + 1]);
            }
            char* dsth = smc + SA_H_B + lr * 80 + lq * 32;
            char* dstl = smc + SA_L_B + lr * 80 + lq * 32;
            ((uint4*)dsth)[0] = make_uint4(hb[0], hb[1], hb[2], hb[3]);
            ((uint4*)dsth)[1] = make_uint4(hb[4], hb[5], hb[6], hb[7]);
            ((uint4*)dstl)[0] = make_uint4(lb[0], lb[1], lb[2], lb[3]);
            ((uint4*)dstl)[1] = make_uint4(lb[4], lb[5], lb[6], lb[7]);
            // ---- load B (pre-split W^T) 128x32 ----
            const uint4* Bh = (const uint4*)(g_WT_hi + woff + (size_t)(n0 + lr) * DMODEL + kb * 32 + lq * 16);
            const uint4* Bl = (const uint4*)(g_WT_lo + woff + (size_t)(n0 + lr) * DMODEL + kb * 32 + lq * 16);
            ((uint4*)(smc + SB_H_B + lr * 80 + lq * 32))[0] = Bh[0];
            ((uint4*)(smc + SB_H_B + lr * 80 + lq * 32))[1] = Bh[1];
            ((uint4*)(smc + SB_L_B + lr * 80 + lq * 32))[0] = Bl[0];
            ((uint4*)(smc + SB_L_B + lr * 80 + lq * 32))[1] = Bl[1];
        }
        __syncthreads();

#pragma unroll
        for (int c2 = 0; c2 < 2; c2++) {
            uint32_t ah[2][4], al[2][4];
#pragma unroll
            for (int mb = 0; mb < 2; mb++) {
                ldm_x4(sb + SA_H_B + aBase + mb * 1280 + c2 * 32, ah[mb]);
                ldm_x4(sb + SA_L_B + aBase + mb * 1280 + c2 * 32, al[mb]);
            }
#pragma unroll
            for (int jj = 0; jj < 4; jj++) {
                uint32_t r4[4];
                ldm_x4(sb + SB_H_B + bBase + jj * 1280 + c2 * 32, r4);
#pragma unroll
                for (int mb = 0; mb < 2; mb++) {
                    mma_bf16(c[mb][2 * jj], ah[mb], r4[0], r4[1]);
                    mma_bf16(c[mb][2 * jj + 1], ah[mb], r4[2], r4[3]);
                    mma_bf16(c[mb][2 * jj], al[mb], r4[0], r4[1]);
                    mma_bf16(c[mb][2 * jj + 1], al[mb], r4[2], r4[3]);
                }
            }
#pragma unroll
            for (int jj = 0; jj < 4; jj++) {
                uint32_t r4[4];
                ldm_x4(sb + SB_L_B + bBase + jj * 1280 + c2 * 32, r4);
#pragma unroll
                for (int mb = 0; mb < 2; mb++) {
                    mma_bf16(c[mb][2 * jj], ah[mb], r4[0], r4[1]);
                    mma_bf16(c[mb][2 * jj + 1], ah[mb], r4[2], r4[3]);
                }
            }
        }
        __syncthreads();
    }

    // ---- epilogue: split-bf16 store ----
#pragma unroll
    for (int mb = 0; mb < 2; mb++) {
#pragma unroll
        for (int j = 0; j < 8; j++) {
            const int R0 = m0 + wm * 32 + mb * 16 + g;
            const int col = n0 + wn * 64 + 8 * j + 2 * t4;
            uint32_t hi, lo;
            split2(c[mb][j][0], c[mb][j][1], hi, lo);
            *(uint32_t*)(Ch + (size_t)R0 * DMODEL + col) = hi;
            *(uint32_t*)(Cl + (size_t)R0 * DMODEL + col) = lo;
            split2(c[mb][j][2], c[mb][j][3], hi, lo);
            *(uint32_t*)(Ch + (size_t)(R0 + 8) * DMODEL + col) = hi;
            *(uint32_t*)(Cl + (size_t)(R0 + 8) * DMODEL + col) = lo;
        }
    }
}

// ===========================================================================
// Flash attention, FA2-style register-resident, mma.sync split-bf16.
// CTA: 128 Q rows x (b,h). 8 warps, warp w owns rows 16w..16w+15.
// ===========================================================================
#define AW 72                    // smem row stride (bf16) -> 144 bytes
#define QH_B 0
#define QL_B 18432
#define KH_B 36864
#define KL_B 55296
#define VH_B 73728
#define VL_B 92160
#define ATTN_SMEM 110592

__global__ __launch_bounds__(256, 1) void attn_mma(float* __restrict__ out)
{
    extern __shared__ char smc[];
    const uint32_t sb = smem_u32(smc);
    const int tid = threadIdx.x;
    const int lane = tid & 31;
    const int w = tid >> 5;
    const int g = lane >> 2, t4 = lane & 3;

    const int q0 = blockIdx.x * 128;
    const int h = blockIdx.y, b = blockIdx.z;
    const int hoff = h * HDIM;

    const int lr = tid >> 1, lq = tid & 1;

    // ---- load Q tile (split) ----
    {
        const size_t grow = (size_t)(b * SEQ + q0 + lr) * DMODEL + hoff;
        const uint4* gqh = (const uint4*)(g_Qh + grow) + lq * 4;
        const uint4* gql = (const uint4*)(g_Ql + grow) + lq * 4;
        char* dh = smc + QH_B + lr * 144 + lq * 64;
        char* dl = smc + QL_B + lr * 144 + lq * 64;
#pragma unroll
        for (int i = 0; i < 4; i++) {
            ((uint4*)dh)[i] = gqh[i];
            ((uint4*)dl)[i] = gql[i];
        }
    }

    float m0 = -1e30f, m1 = -1e30f, l0 = 0.0f, l1 = 0.0f;
    float O[8][4];
#pragma unroll
    for (int j = 0; j < 8; j++)
#pragma unroll
        for (int i = 0; i < 4; i++) O[j][i] = 0.0f;

    // per-lane ldmatrix base byte offsets
    const uint32_t qBase = (uint32_t)(16 * w + (lane & 15)) * 144 + (lane >> 4) * 16;
    const uint32_t kBase = (uint32_t)((lane & 7) + ((lane >> 4) << 3)) * 144
                           + ((lane >> 3) & 1) * 16;
    const uint32_t vBase = (uint32_t)((lane & 7) + (((lane >> 3) & 1) << 3)) * 144
                           + (lane >> 4) * 16;

    __syncthreads();

    for (int kt = 0; kt < SEQ / 128; kt++) {
        // ---- load K/V tiles (split) ----
        {
            const size_t grow = (size_t)(b * SEQ + kt * 128 + lr) * DMODEL + hoff;
            const uint4* gkh = (const uint4*)(g_Kh + grow) + lq * 4;
            const uint4* gkl = (const uint4*)(g_Kl + grow) + lq * 4;
            const uint4* gvh = (const uint4*)(g_Vh + grow) + lq * 4;
            const uint4* gvl = (const uint4*)(g_Vl + grow) + lq * 4;
            char* dkh = smc + KH_B + lr * 144 + lq * 64;
            char* dkl = smc + KL_B + lr * 144 + lq * 64;
            char* dvh = smc + VH_B + lr * 144 + lq * 64;
            char* dvl = smc + VL_B + lr * 144 + lq * 64;
#pragma unroll
            for (int i = 0; i < 4; i++) {
                ((uint4*)dkh)[i] = gkh[i];
                ((uint4*)dkl)[i] = gkl[i];
                ((uint4*)dvh)[i] = gvh[i];
                ((uint4*)dvl)[i] = gvl[i];
            }
        }
        __syncthreads();

        // ---- S = Q K^T  (raw, unscaled), split-bf16 3-term ----
        float S[16][4];
#pragma unroll
        for (int j = 0; j < 16; j++)
#pragma unroll
            for (int i = 0; i < 4; i++) S[j][i] = 0.0f;

#pragma unroll
        for (int c = 0; c < 4; c++) {
            uint32_t aqh[4], aql[4];
            ldm_x4(sb + QH_B + qBase + c * 32, aqh);
            ldm_x4(sb + QL_B + qBase + c * 32, aql);
#pragma unroll
            for (int jj = 0; jj < 8; jj++) {
                uint32_t r4[4];
                ldm_x4(sb + KH_B + kBase + jj * 2304 + c * 32, r4);
                mma_bf16(S[2 * jj], aqh, r4[0], r4[1]);
                mma_bf16(S[2 * jj + 1], aqh, r4[2], r4[3]);
                mma_bf16(S[2 * jj], aql, r4[0], r4[1]);
                mma_bf16(S[2 * jj + 1], aql, r4[2], r4[3]);
            }
#pragma unroll
            for (int jj = 0; jj < 8; jj++) {
                uint32_t r4[4];
                ldm_x4(sb + KL_B + kBase + jj * 2304 + c * 32, r4);
                mma_bf16(S[2 * jj], aqh, r4[0], r4[1]);
                mma_bf16(S[2 * jj + 1], aqh, r4[2], r4[3]);
            }
        }

        // ---- online softmax in registers ----
        float mx0 = -1e30f, mx1 = -1e30f;
#pragma unroll
        for (int j = 0; j < 16; j++) {
            mx0 = fmaxf(mx0, fmaxf(S[j][0], S[j][1]));
            mx1 = fmaxf(mx1, fmaxf(S[j][2], S[j][3]));
        }
        mx0 = fmaxf(mx0, __shfl_xor_sync(0xffffffffu, mx0, 1));
        mx0 = fmaxf(mx0, __shfl_xor_sync(0xffffffffu, mx0, 2));
        mx1 = fmaxf(mx1, __shfl_xor_sync(0xffffffffu, mx1, 1));
        mx1 = fmaxf(mx1, __shfl_xor_sync(0xffffffffu, mx1, 2));
        const float mn0 = fmaxf(m0, mx0), mn1 = fmaxf(m1, mx1);
        const float al0 = ex2((m0 - mn0) * CEXP);
        const float al1 = ex2((m1 - mn1) * CEXP);
        m0 = mn0; m1 = mn1;

        float s0 = 0.0f, s1 = 0.0f;
#pragma unroll
        for (int j = 0; j < 16; j++) {
            S[j][0] = ex2((S[j][0] - m0) * CEXP);
            S[j][1] = ex2((S[j][1] - m0) * CEXP);
            S[j][2] = ex2((S[j][2] - m1) * CEXP);
            S[j][3] = ex2((S[j][3] - m1) * CEXP);
            s0 += S[j][0] + S[j][1];
            s1 += S[j][2] + S[j][3];
        }
        s0 += __shfl_xor_sync(0xffffffffu, s0, 1);
        s0 += __shfl_xor_sync(0xffffffffu, s0, 2);
        s1 += __shfl_xor_sync(0xffffffffu, s1, 1);
        s1 += __shfl_xor_sync(0xffffffffu, s1, 2);
        l0 = l0 * al0 + s0;
        l1 = l1 * al1 + s1;

#pragma unroll
        for (int j = 0; j < 8; j++) {
            O[j][0] *= al0; O[j][1] *= al0;
            O[j][2] *= al1; O[j][3] *= al1;
        }

        // ---- O += P V   (P from S regs, split-bf16 3-term; V via ldmatrix.trans) ----
#pragma unroll
        for (int c = 0; c < 8; c++) {
            uint32_t ph[4], pl[4];
            split2(S[2 * c][0], S[2 * c][1], ph[0], pl[0]);
            split2(S[2 * c][2], S[2 * c][3], ph[1], pl[1]);
            split2(S[2 * c + 1][0], S[2 * c + 1][1], ph[2], pl[2]);
            split2(S[2 * c + 1][2], S[2 * c + 1][3], ph[3], pl[3]);
#pragma unroll
            for (int jj = 0; jj < 4; jj++) {
                uint32_t r4[4];
                ldm_x4t(sb + VH_B + vBase + c * 2304 + jj * 32, r4);
                mma_bf16(O[2 * jj], ph, r4[0], r4[1]);
                mma_bf16(O[2 * jj + 1], ph, r4[2], r4[3]);
                mma_bf16(O[2 * jj], pl, r4[0], r4[1]);
                mma_bf16(O[2 * jj + 1], pl, r4[2], r4[3]);
            }
#pragma unroll
            for (int jj = 0; jj < 4; jj++) {
                uint32_t r4[4];
                ldm_x4t(sb + VL_B + vBase + c * 2304 + jj * 32, r4);
                mma_bf16(O[2 * jj], ph, r4[0], r4[1]);
                mma_bf16(O[2 * jj + 1], ph, r4[2], r4[3]);
            }
        }
        __syncthreads();
    }

    // ---- epilogue ----
    const float i0 = 1.0f / l0;
    const float i1 = 1.0f / l1;
    const size_t R0 = (size_t)(b * SEQ + q0 + 16 * w + g);
#pragma unroll
    for (int j = 0; j < 8; j++) {
        const int col = hoff + 8 * j + 2 * t4;
        *(float2*)&out[R0 * DMODEL + col] = make_float2(O[j][0] * i0, O[j][1] * i0);
        *(float2*)&out[(R0 + 8) * DMODEL + col] = make_float2(O[j][2] * i1, O[j][3] * i1);
    }
}

// ===========================================================================
// kernel_launch
// ===========================================================================
extern "C" void kernel_launch(void* const* d_in, const int* in_sizes, int n_in,
                              void* d_out, int out_size)
{
    const float* q  = (const float*)d_in[0];
    const float* k  = (const float*)d_in[1];
    const float* v  = (const float*)d_in[2];
    const float* Wq = (const float*)d_in[3];
    const float* Wk = (const float*)d_in[4];
    const float* Wv = (const float*)d_in[5];
    float* out = (float*)d_out;

    wt_convert<<<dim3(32, 32, 3), dim3(32, 8)>>>(Wq, Wk, Wv);

    cudaFuncSetAttribute(proj_mma, cudaFuncAttributeMaxDynamicSharedMemorySize, PROJ_SMEM);
    proj_mma<<<dim3(DMODEL / 128, (BATCH * SEQ) / 128, 3), 256, PROJ_SMEM>>>(q, k, v);

    cudaFuncSetAttribute(attn_mma, cudaFuncAttributeMaxDynamicSharedMemorySize, ATTN_SMEM);
    attn_mma<<<dim3(SEQ / 128, NHEADS, BATCH), 256, ATTN_SMEM>>>(out);
}

// round 4
// speedup vs baseline: 2.7445x; 1.1842x over previous
#include <cuda_runtime.h>
#include <cuda_bf16.h>
#include <cstdint>

// Problem constants
#define BATCH   2
#define SEQ     2048
#define DMODEL  1024
#define NHEADS  16
#define HDIM    64
#define CEXP    92.33248261689366f   // SCALE(=64) * log2(e)

// Scratch: W^T split-bf16, projected Q/K/V split-bf16
__device__ __nv_bfloat16 g_WT_hi[3 * DMODEL * DMODEL];
__device__ __nv_bfloat16 g_WT_lo[3 * DMODEL * DMODEL];
__device__ __nv_bfloat16 g_Qh[BATCH * SEQ * DMODEL];
__device__ __nv_bfloat16 g_Ql[BATCH * SEQ * DMODEL];
__device__ __nv_bfloat16 g_Kh[BATCH * SEQ * DMODEL];
__device__ __nv_bfloat16 g_Kl[BATCH * SEQ * DMODEL];
__device__ __nv_bfloat16 g_Vh[BATCH * SEQ * DMODEL];
__device__ __nv_bfloat16 g_Vl[BATCH * SEQ * DMODEL];

// ===========================================================================
// Helpers (sm_80-era PTX only: valid on plain compute_103 target)
// ===========================================================================
__device__ __forceinline__ uint32_t smem_u32(const void* p) {
    uint32_t a;
    asm("{ .reg .u64 t; cvta.to.shared.u64 t, %1; cvt.u32.u64 %0, t; }" : "=r"(a) : "l"(p));
    return a;
}
__device__ __forceinline__ void ldm_x4(uint32_t addr, uint32_t* r) {
    asm volatile("ldmatrix.sync.aligned.m8n8.x4.shared.b16 {%0,%1,%2,%3}, [%4];"
                 : "=r"(r[0]), "=r"(r[1]), "=r"(r[2]), "=r"(r[3]) : "r"(addr));
}
__device__ __forceinline__ void ldm_x4t(uint32_t addr, uint32_t* r) {
    asm volatile("ldmatrix.sync.aligned.m8n8.x4.trans.shared.b16 {%0,%1,%2,%3}, [%4];"
                 : "=r"(r[0]), "=r"(r[1]), "=r"(r[2]), "=r"(r[3]) : "r"(addr));
}
__device__ __forceinline__ void mma_bf16(float* c, const uint32_t* a, uint32_t b0, uint32_t b1) {
    asm volatile("mma.sync.aligned.m16n8k16.row.col.f32.bf16.bf16.f32 "
                 "{%0,%1,%2,%3}, {%4,%5,%6,%7}, {%8,%9}, {%0,%1,%2,%3};"
                 : "+f"(c[0]), "+f"(c[1]), "+f"(c[2]), "+f"(c[3])
                 : "r"(a[0]), "r"(a[1]), "r"(a[2]), "r"(a[3]), "r"(b0), "r"(b1));
}
__device__ __forceinline__ void split2(float p0, float p1, uint32_t& hi, uint32_t& lo) {
    asm("cvt.rn.bf16x2.f32 %0, %1, %2;" : "=r"(hi) : "f"(p1), "f"(p0));
    float h0 = __uint_as_float(hi << 16);
    float h1 = __uint_as_float(hi & 0xFFFF0000u);
    float l0 = p0 - h0;
    float l1 = p1 - h1;
    asm("cvt.rn.bf16x2.f32 %0, %1, %2;" : "=r"(lo) : "f"(l1), "f"(l0));
}
__device__ __forceinline__ float ex2(float x) {
    float r;
    asm("ex2.approx.f32 %0, %1;" : "=f"(r) : "f"(x));
    return r;
}
__device__ __forceinline__ void cpa16(uint32_t s, const void* g) {
    asm volatile("cp.async.cg.shared.global [%0], [%1], 16;" :: "r"(s), "l"(g));
}
#define CP_COMMIT() asm volatile("cp.async.commit_group;" ::: "memory")
#define CP_WAIT1()  asm volatile("cp.async.wait_group 1;" ::: "memory")
#define CP_WAIT0()  asm volatile("cp.async.wait_group 0;" ::: "memory")

// ===========================================================================
// W transpose + split-bf16 convert:  g_WT[z][n][k] = W_z[k][n]
// ===========================================================================
__global__ void wt_convert(const float* __restrict__ Wq, const float* __restrict__ Wk,
                           const float* __restrict__ Wv)
{
    __shared__ float tile[32][33];
    const float* W = (blockIdx.z == 0) ? Wq : (blockIdx.z == 1) ? Wk : Wv;
    const int tx = threadIdx.x, ty = threadIdx.y;
    const int k0 = blockIdx.y * 32, n0 = blockIdx.x * 32;
#pragma unroll
    for (int i = 0; i < 4; i++)
        tile[ty + i * 8][tx] = W[(size_t)(k0 + ty + i * 8) * DMODEL + n0 + tx];
    __syncthreads();
    const size_t base = (size_t)blockIdx.z * DMODEL * DMODEL;
#pragma unroll
    for (int i = 0; i < 4; i++) {
        const int n = n0 + ty + i * 8;
        const int k = k0 + tx;
        const float v = tile[tx][ty + i * 8];
        __nv_bfloat16 h = __float2bfloat16(v);
        float lo = v - __bfloat162float(h);
        g_WT_hi[base + (size_t)n * DMODEL + k] = h;
        g_WT_lo[base + (size_t)n * DMODEL + k] = __float2bfloat16(lo);
    }
}

// ===========================================================================
// Projection GEMM (mma.sync, split-bf16 3-term), 2-stage pipeline:
//   cp.async for B (pre-split W^T), register-prefetch + convert for A.
// CTA 128x128, 8 warps (4m x 2n), warp tile 32x64, BK=32.
// Stage layout (bytes): AH 0, AL 10240, BH 20480, BL 30720; stage size 40960.
// ===========================================================================
#define PSTG 40960
#define PROJ_SMEM (2 * PSTG)

__global__ __launch_bounds__(256) void proj_mma(const float* __restrict__ qi,
                                                const float* __restrict__ ki,
                                                const float* __restrict__ vi)
{
    extern __shared__ char smc[];
    const uint32_t sb = smem_u32(smc);
    const int tid = threadIdx.x;
    const int lane = tid & 31;
    const int wid = tid >> 5;
    const int g = lane >> 2, t4 = lane & 3;
    const int wm = wid & 3, wn = wid >> 2;

    const float* A;
    __nv_bfloat16 *Ch, *Cl;
    if (blockIdx.z == 0)      { A = qi; Ch = g_Qh; Cl = g_Ql; }
    else if (blockIdx.z == 1) { A = ki; Ch = g_Kh; Cl = g_Kl; }
    else                      { A = vi; Ch = g_Vh; Cl = g_Vl; }
    const size_t woff = (size_t)blockIdx.z * DMODEL * DMODEL;
    const char* BhG = (const char*)(g_WT_hi + woff);
    const char* BlG = (const char*)(g_WT_lo + woff);

    const int m0 = blockIdx.y * 128;
    const int n0 = blockIdx.x * 128;

    float c[2][8][4];
#pragma unroll
    for (int mb = 0; mb < 2; mb++)
#pragma unroll
        for (int j = 0; j < 8; j++)
#pragma unroll
            for (int i = 0; i < 4; i++) c[mb][j][i] = 0.0f;

    const uint32_t aBase = (uint32_t)(wm * 32 + (lane & 15)) * 80 + (lane >> 4) * 16;
    const uint32_t bBase = (uint32_t)(wn * 64 + (lane & 7) + ((lane >> 4) << 3)) * 80
                           + ((lane >> 3) & 1) * 16;

    const int lr = tid >> 1, lq = tid & 1;
    const size_t aRow = (size_t)(m0 + lr) * DMODEL;
    const size_t bRowB = (size_t)(n0 + lr) * DMODEL * 2;  // bytes
    const uint32_t ldB = lr * 80 + lq * 32;               // smem store base (bytes)

    // ---- prologue: A(0) -> regs; B(0) -> stage 0 via cp.async ----
    float4 aCur[4], aNext[4];
#pragma unroll
    for (int i = 0; i < 4; i++)
        aCur[i] = ((const float4*)(A + aRow + lq * 16))[i];
#pragma unroll
    for (int j = 0; j < 2; j++) {
        cpa16(sb + 20480 + ldB + j * 16, BhG + bRowB + lq * 32 + j * 16);
        cpa16(sb + 30720 + ldB + j * 16, BlG + bRowB + lq * 32 + j * 16);
    }
    CP_COMMIT();

#pragma unroll 2
    for (int kb = 0; kb < 32; kb++) {
        const uint32_t stg = (uint32_t)(kb & 1) * PSTG;
        // convert + store current A chunk
        {
            uint32_t hb[8], lb[8];
#pragma unroll
            for (int i = 0; i < 4; i++) {
                split2(aCur[i].x, aCur[i].y, hb[2 * i], lb[2 * i]);
                split2(aCur[i].z, aCur[i].w, hb[2 * i + 1], lb[2 * i + 1]);
            }
            char* dh = smc + stg + ldB;
            char* dl = smc + stg + 10240 + ldB;
            ((uint4*)dh)[0] = make_uint4(hb[0], hb[1], hb[2], hb[3]);
            ((uint4*)dh)[1] = make_uint4(hb[4], hb[5], hb[6], hb[7]);
            ((uint4*)dl)[0] = make_uint4(lb[0], lb[1], lb[2], lb[3]);
            ((uint4*)dl)[1] = make_uint4(lb[4], lb[5], lb[6], lb[7]);
        }
        // prefetch next chunk
        if (kb + 1 < 32) {
            const uint32_t ns = (uint32_t)((kb + 1) & 1) * PSTG;
            const int ko = (kb + 1) * 32;
#pragma unroll
            for (int i = 0; i < 4; i++)
                aNext[i] = ((const float4*)(A + aRow + ko + lq * 16))[i];
#pragma unroll
            for (int j = 0; j < 2; j++) {
                cpa16(sb + ns + 20480 + ldB + j * 16, BhG + bRowB + ko * 2 + lq * 32 + j * 16);
                cpa16(sb + ns + 30720 + ldB + j * 16, BlG + bRowB + ko * 2 + lq * 32 + j * 16);
            }
            CP_COMMIT();
            CP_WAIT1();
        } else {
            CP_WAIT0();
        }
        __syncthreads();

#pragma unroll
        for (int c2 = 0; c2 < 2; c2++) {
            uint32_t ah[2][4], al[2][4];
#pragma unroll
            for (int mb = 0; mb < 2; mb++) {
                ldm_x4(sb + stg + aBase + mb * 1280 + c2 * 32, ah[mb]);
                ldm_x4(sb + stg + 10240 + aBase + mb * 1280 + c2 * 32, al[mb]);
            }
#pragma unroll
            for (int jj = 0; jj < 4; jj++) {
                uint32_t r4[4];
                ldm_x4(sb + stg + 20480 + bBase + jj * 1280 + c2 * 32, r4);
#pragma unroll
                for (int mb = 0; mb < 2; mb++) {
                    mma_bf16(c[mb][2 * jj], ah[mb], r4[0], r4[1]);
                    mma_bf16(c[mb][2 * jj + 1], ah[mb], r4[2], r4[3]);
                    mma_bf16(c[mb][2 * jj], al[mb], r4[0], r4[1]);
                    mma_bf16(c[mb][2 * jj + 1], al[mb], r4[2], r4[3]);
                }
            }
#pragma unroll
            for (int jj = 0; jj < 4; jj++) {
                uint32_t r4[4];
                ldm_x4(sb + stg + 30720 + bBase + jj * 1280 + c2 * 32, r4);
#pragma unroll
                for (int mb = 0; mb < 2; mb++) {
                    mma_bf16(c[mb][2 * jj], ah[mb], r4[0], r4[1]);
                    mma_bf16(c[mb][2 * jj + 1], ah[mb], r4[2], r4[3]);
                }
            }
        }
        __syncthreads();
#pragma unroll
        for (int i = 0; i < 4; i++) aCur[i] = aNext[i];
    }

    // ---- epilogue: split-bf16 store ----
#pragma unroll
    for (int mb = 0; mb < 2; mb++) {
#pragma unroll
        for (int j = 0; j < 8; j++) {
            const int R0 = m0 + wm * 32 + mb * 16 + g;
            const int col = n0 + wn * 64 + 8 * j + 2 * t4;
            uint32_t hi, lo;
            split2(c[mb][j][0], c[mb][j][1], hi, lo);
            *(uint32_t*)(Ch + (size_t)R0 * DMODEL + col) = hi;
            *(uint32_t*)(Cl + (size_t)R0 * DMODEL + col) = lo;
            split2(c[mb][j][2], c[mb][j][3], hi, lo);
            *(uint32_t*)(Ch + (size_t)(R0 + 8) * DMODEL + col) = hi;
            *(uint32_t*)(Cl + (size_t)(R0 + 8) * DMODEL + col) = lo;
        }
    }
}

// ===========================================================================
// Flash attention, register-resident, mma.sync split-bf16, 2-stage cp.async.
// CTA: 128 Q rows x (b,h). 8 warps, warp w owns rows 16w..16w+15.
// smem: QH 0, QL 18432; KV stage s at 36864 + s*73728:
//       {KH +0, KL +18432, VH +36864, VL +55296}. Total 184320 B.
// ===========================================================================
#define KVB  36864
#define KVST 73728
#define ATTN_SMEM 184320

__global__ __launch_bounds__(256, 1) void attn_mma(float* __restrict__ out)
{
    extern __shared__ char smc[];
    const uint32_t sb = smem_u32(smc);
    const int tid = threadIdx.x;
    const int lane = tid & 31;
    const int w = tid >> 5;
    const int g = lane >> 2, t4 = lane & 3;

    const int q0 = blockIdx.x * 128;
    const int h = blockIdx.y, b = blockIdx.z;
    const int hoff = h * HDIM;

    const int lr = tid >> 1, lq = tid & 1;
    const uint32_t ldKV = lr * 144 + lq * 64;   // per-thread smem store base

    // ---- prefetch KV tile 0 into stage 0 ----
    {
        const size_t gB = ((size_t)(b * SEQ + lr) * DMODEL + hoff) * 2 + lq * 64;
        const uint32_t d = sb + KVB + ldKV;
#pragma unroll
        for (int i = 0; i < 4; i++) {
            cpa16(d + i * 16,         (const char*)g_Kh + gB + i * 16);
            cpa16(d + 18432 + i * 16, (const char*)g_Kl + gB + i * 16);
            cpa16(d + 36864 + i * 16, (const char*)g_Vh + gB + i * 16);
            cpa16(d + 55296 + i * 16, (const char*)g_Vl + gB + i * 16);
        }
        CP_COMMIT();
    }

    // ---- load Q tile (split) ----
    {
        const size_t grow = (size_t)(b * SEQ + q0 + lr) * DMODEL + hoff;
        const uint4* gqh = (const uint4*)(g_Qh + grow) + lq * 4;
        const uint4* gql = (const uint4*)(g_Ql + grow) + lq * 4;
        char* dh = smc + lr * 144 + lq * 64;
        char* dl = smc + 18432 + lr * 144 + lq * 64;
#pragma unroll
        for (int i = 0; i < 4; i++) {
            ((uint4*)dh)[i] = gqh[i];
            ((uint4*)dl)[i] = gql[i];
        }
    }

    float m0 = -1e30f, m1 = -1e30f, l0 = 0.0f, l1 = 0.0f;
    float O[8][4];
#pragma unroll
    for (int j = 0; j < 8; j++)
#pragma unroll
        for (int i = 0; i < 4; i++) O[j][i] = 0.0f;

    const uint32_t qBase = (uint32_t)(16 * w + (lane & 15)) * 144 + (lane >> 4) * 16;
    const uint32_t kBase = (uint32_t)((lane & 7) + ((lane >> 4) << 3)) * 144
                           + ((lane >> 3) & 1) * 16;
    const uint32_t vBase = (uint32_t)((lane & 7) + (((lane >> 3) & 1) << 3)) * 144
                           + (lane >> 4) * 16;

    __syncthreads();

    // ---- hoist Q fragments (loop-invariant) ----
    uint32_t aqh[4][4], aql[4][4];
#pragma unroll
    for (int c = 0; c < 4; c++) {
        ldm_x4(sb + qBase + c * 32, aqh[c]);
        ldm_x4(sb + 18432 + qBase + c * 32, aql[c]);
    }

#pragma unroll 2
    for (int kt = 0; kt < SEQ / 128; kt++) {
        const uint32_t kv = sb + KVB + (uint32_t)(kt & 1) * KVST;

        // prefetch next KV tile
        if (kt + 1 < SEQ / 128) {
            const size_t gB = ((size_t)(b * SEQ + (kt + 1) * 128 + lr) * DMODEL + hoff) * 2 + lq * 64;
            const uint32_t d = sb + KVB + (uint32_t)((kt + 1) & 1) * KVST + ldKV;
#pragma unroll
            for (int i = 0; i < 4; i++) {
                cpa16(d + i * 16,         (const char*)g_Kh + gB + i * 16);
                cpa16(d + 18432 + i * 16, (const char*)g_Kl + gB + i * 16);
                cpa16(d + 36864 + i * 16, (const char*)g_Vh + gB + i * 16);
                cpa16(d + 55296 + i * 16, (const char*)g_Vl + gB + i * 16);
            }
            CP_COMMIT();
            CP_WAIT1();
        } else {
            CP_WAIT0();
        }
        __syncthreads();

        // ---- S = Q K^T (raw), split-bf16 3-term ----
        float S[16][4];
#pragma unroll
        for (int j = 0; j < 16; j++)
#pragma unroll
            for (int i = 0; i < 4; i++) S[j][i] = 0.0f;

#pragma unroll
        for (int c = 0; c < 4; c++) {
#pragma unroll
            for (int jj = 0; jj < 8; jj++) {
                uint32_t r4[4];
                ldm_x4(kv + kBase + jj * 2304 + c * 32, r4);
                mma_bf16(S[2 * jj], aqh[c], r4[0], r4[1]);
                mma_bf16(S[2 * jj + 1], aqh[c], r4[2], r4[3]);
                mma_bf16(S[2 * jj], aql[c], r4[0], r4[1]);
                mma_bf16(S[2 * jj + 1], aql[c], r4[2], r4[3]);
            }
#pragma unroll
            for (int jj = 0; jj < 8; jj++) {
                uint32_t r4[4];
                ldm_x4(kv + 18432 + kBase + jj * 2304 + c * 32, r4);
                mma_bf16(S[2 * jj], aqh[c], r4[0], r4[1]);
                mma_bf16(S[2 * jj + 1], aqh[c], r4[2], r4[3]);
            }
        }

        // ---- online softmax in registers ----
        float mx0 = -1e30f, mx1 = -1e30f;
#pragma unroll
        for (int j = 0; j < 16; j++) {
            mx0 = fmaxf(mx0, fmaxf(S[j][0], S[j][1]));
            mx1 = fmaxf(mx1, fmaxf(S[j][2], S[j][3]));
        }
        mx0 = fmaxf(mx0, __shfl_xor_sync(0xffffffffu, mx0, 1));
        mx0 = fmaxf(mx0, __shfl_xor_sync(0xffffffffu, mx0, 2));
        mx1 = fmaxf(mx1, __shfl_xor_sync(0xffffffffu, mx1, 1));
        mx1 = fmaxf(mx1, __shfl_xor_sync(0xffffffffu, mx1, 2));
        const float mn0 = fmaxf(m0, mx0), mn1 = fmaxf(m1, mx1);
        const float al0 = ex2((m0 - mn0) * CEXP);
        const float al1 = ex2((m1 - mn1) * CEXP);
        m0 = mn0; m1 = mn1;

        float s0 = 0.0f, s1 = 0.0f;
#pragma unroll
        for (int j = 0; j < 16; j++) {
            S[j][0] = ex2((S[j][0] - m0) * CEXP);
            S[j][1] = ex2((S[j][1] - m0) * CEXP);
            S[j][2] = ex2((S[j][2] - m1) * CEXP);
            S[j][3] = ex2((S[j][3] - m1) * CEXP);
            s0 += S[j][0] + S[j][1];
            s1 += S[j][2] + S[j][3];
        }
        s0 += __shfl_xor_sync(0xffffffffu, s0, 1);
        s0 += __shfl_xor_sync(0xffffffffu, s0, 2);
        s1 += __shfl_xor_sync(0xffffffffu, s1, 1);
        s1 += __shfl_xor_sync(0xffffffffu, s1, 2);
        l0 = l0 * al0 + s0;
        l1 = l1 * al1 + s1;

#pragma unroll
        for (int j = 0; j < 8; j++) {
            O[j][0] *= al0; O[j][1] *= al0;
            O[j][2] *= al1; O[j][3] *= al1;
        }

        // ---- O += P V (split-bf16 3-term; V via ldmatrix.trans) ----
#pragma unroll
        for (int c = 0; c < 8; c++) {
            uint32_t ph[4], pl[4];
            split2(S[2 * c][0], S[2 * c][1], ph[0], pl[0]);
            split2(S[2 * c][2], S[2 * c][3], ph[1], pl[1]);
            split2(S[2 * c + 1][0], S[2 * c + 1][1], ph[2], pl[2]);
            split2(S[2 * c + 1][2], S[2 * c + 1][3], ph[3], pl[3]);
#pragma unroll
            for (int jj = 0; jj < 4; jj++) {
                uint32_t r4[4];
                ldm_x4t(kv + 36864 + vBase + c * 2304 + jj * 32, r4);
                mma_bf16(O[2 * jj], ph, r4[0], r4[1]);
                mma_bf16(O[2 * jj + 1], ph, r4[2], r4[3]);
                mma_bf16(O[2 * jj], pl, r4[0], r4[1]);
                mma_bf16(O[2 * jj + 1], pl, r4[2], r4[3]);
            }
#pragma unroll
            for (int jj = 0; jj < 4; jj++) {
                uint32_t r4[4];
                ldm_x4t(kv + 55296 + vBase + c * 2304 + jj * 32, r4);
                mma_bf16(O[2 * jj], ph, r4[0], r4[1]);
                mma_bf16(O[2 * jj + 1], ph, r4[2], r4[3]);
            }
        }
        __syncthreads();
    }

    // ---- epilogue ----
    const float i0 = 1.0f / l0;
    const float i1 = 1.0f / l1;
    const size_t R0 = (size_t)(b * SEQ + q0 + 16 * w + g);
#pragma unroll
    for (int j = 0; j < 8; j++) {
        const int col = hoff + 8 * j + 2 * t4;
        *(float2*)&out[R0 * DMODEL + col] = make_float2(O[j][0] * i0, O[j][1] * i0);
        *(float2*)&out[(R0 + 8) * DMODEL + col] = make_float2(O[j][2] * i1, O[j][3] * i1);
    }
}

// ===========================================================================
// kernel_launch
// ===========================================================================
extern "C" void kernel_launch(void* const* d_in, const int* in_sizes, int n_in,
                              void* d_out, int out_size)
{
    const float* q  = (const float*)d_in[0];
    const float* k  = (const float*)d_in[1];
    const float* v  = (const float*)d_in[2];
    const float* Wq = (const float*)d_in[3];
    const float* Wk = (const float*)d_in[4];
    const float* Wv = (const float*)d_in[5];
    float* out = (float*)d_out;

    wt_convert<<<dim3(32, 32, 3), dim3(32, 8)>>>(Wq, Wk, Wv);

    cudaFuncSetAttribute(proj_mma, cudaFuncAttributeMaxDynamicSharedMemorySize, PROJ_SMEM);
    proj_mma<<<dim3(DMODEL / 128, (BATCH * SEQ) / 128, 3), 256, PROJ_SMEM>>>(q, k, v);

    cudaFuncSetAttribute(attn_mma, cudaFuncAttributeMaxDynamicSharedMemorySize, ATTN_SMEM);
    attn_mma<<<dim3(SEQ / 128, NHEADS, BATCH), 256, ATTN_SMEM>>>(out);
}

// round 5
// speedup vs baseline: 3.7045x; 1.3498x over previous
#include <cuda_runtime.h>
#include <cuda_fp16.h>
#include <cstdint>

// Problem constants
#define BATCH   2
#define SEQ     2048
#define DMODEL  1024
#define NHEADS  16
#define HDIM    64
#define CEXP    92.33248261689366f   // SCALE(=64) * log2(e)

// Scratch: W^T split-fp16 planes; Q/K split-fp16; V single fp16 plane
__device__ __half g_WT_hi[3 * DMODEL * DMODEL];
__device__ __half g_WT_lo[3 * DMODEL * DMODEL];
__device__ __half g_Qh[BATCH * SEQ * DMODEL];
__device__ __half g_Ql[BATCH * SEQ * DMODEL];
__device__ __half g_Kh[BATCH * SEQ * DMODEL];
__device__ __half g_Kl[BATCH * SEQ * DMODEL];
__device__ __half g_Vh[BATCH * SEQ * DMODEL];

// ===========================================================================
// Helpers (sm_80-era PTX only: valid on plain compute_103 target)
// ===========================================================================
__device__ __forceinline__ uint32_t smem_u32(const void* p) {
    uint32_t a;
    asm("{ .reg .u64 t; cvta.to.shared.u64 t, %1; cvt.u32.u64 %0, t; }" : "=r"(a) : "l"(p));
    return a;
}
__device__ __forceinline__ void ldm_x4(uint32_t addr, uint32_t* r) {
    asm volatile("ldmatrix.sync.aligned.m8n8.x4.shared.b16 {%0,%1,%2,%3}, [%4];"
                 : "=r"(r[0]), "=r"(r[1]), "=r"(r[2]), "=r"(r[3]) : "r"(addr));
}
__device__ __forceinline__ void ldm_x4t(uint32_t addr, uint32_t* r) {
    asm volatile("ldmatrix.sync.aligned.m8n8.x4.trans.shared.b16 {%0,%1,%2,%3}, [%4];"
                 : "=r"(r[0]), "=r"(r[1]), "=r"(r[2]), "=r"(r[3]) : "r"(addr));
}
// D += A * B^T  (m16n8k16, fp16 in, f32 acc)
__device__ __forceinline__ void mma_f16(float* c, const uint32_t* a, uint32_t b0, uint32_t b1) {
    asm volatile("mma.sync.aligned.m16n8k16.row.col.f32.f16.f16.f32 "
                 "{%0,%1,%2,%3}, {%4,%5,%6,%7}, {%8,%9}, {%0,%1,%2,%3};"
                 : "+f"(c[0]), "+f"(c[1]), "+f"(c[2]), "+f"(c[3])
                 : "r"(a[0]), "r"(a[1]), "r"(a[2]), "r"(a[3]), "r"(b0), "r"(b1));
}
// pack two fp32 -> fp16x2
__device__ __forceinline__ uint32_t pack_h2(float p0, float p1) {
    uint32_t h;
    asm("cvt.rn.f16x2.f32 %0, %1, %2;" : "=r"(h) : "f"(p1), "f"(p0));
    return h;
}
// split two fp32 into fp16x2 hi + lo planes
__device__ __forceinline__ void split2h(float p0, float p1, uint32_t& hi, uint32_t& lo) {
    uint32_t h = pack_h2(p0, p1);
    float f0, f1;
    asm("{.reg .b16 a,b; mov.b32 {a,b}, %2; cvt.f32.f16 %0, a; cvt.f32.f16 %1, b;}"
        : "=f"(f0), "=f"(f1) : "r"(h));
    hi = h;
    lo = pack_h2(p0 - f0, p1 - f1);
}
__device__ __forceinline__ float ex2(float x) {
    float r;
    asm("ex2.approx.f32 %0, %1;" : "=f"(r) : "f"(x));
    return r;
}
__device__ __forceinline__ void cpa16(uint32_t s, const void* g) {
    asm volatile("cp.async.cg.shared.global [%0], [%1], 16;" :: "r"(s), "l"(g));
}
#define CP_COMMIT() asm volatile("cp.async.commit_group;" ::: "memory")
#define CP_WAIT1()  asm volatile("cp.async.wait_group 1;" ::: "memory")
#define CP_WAIT0()  asm volatile("cp.async.wait_group 0;" ::: "memory")

// ===========================================================================
// W transpose + split-fp16 convert:  g_WT[z][n][k] = W_z[k][n]
// ===========================================================================
__global__ void wt_convert(const float* __restrict__ Wq, const float* __restrict__ Wk,
                           const float* __restrict__ Wv)
{
    __shared__ float tile[32][33];
    const float* W = (blockIdx.z == 0) ? Wq : (blockIdx.z == 1) ? Wk : Wv;
    const int tx = threadIdx.x, ty = threadIdx.y;
    const int k0 = blockIdx.y * 32, n0 = blockIdx.x * 32;
#pragma unroll
    for (int i = 0; i < 4; i++)
        tile[ty + i * 8][tx] = W[(size_t)(k0 + ty + i * 8) * DMODEL + n0 + tx];
    __syncthreads();
    const size_t base = (size_t)blockIdx.z * DMODEL * DMODEL;
#pragma unroll
    for (int i = 0; i < 4; i++) {
        const int n = n0 + ty + i * 8;
        const int k = k0 + tx;
        const float v = tile[tx][ty + i * 8];
        __half h = __float2half_rn(v);
        g_WT_hi[base + (size_t)n * DMODEL + k] = h;
        g_WT_lo[base + (size_t)n * DMODEL + k] = __float2half_rn(v - __half2float(h));
    }
}

// ===========================================================================
// Projection GEMM (mma.sync fp16, split 3-term for Q/K, 2-term for V),
// persistent grid (296 CTAs, 768 units), 2-stage cp.async pipeline.
// CTA tile 128x128, 8 warps (4m x 2n), warp tile 32x64, BK=32.
// Stage (bytes): AH 0, AL 10240, BH 20480, BL 30720; stage size 40960.
// ===========================================================================
#define PSTG 40960
#define PROJ_SMEM (2 * PSTG)
#define PROJ_GRID 296
#define PROJ_UNITS 768

__global__ __launch_bounds__(256, 2) void proj_mma(const float* __restrict__ qi,
                                                   const float* __restrict__ ki,
                                                   const float* __restrict__ vi)
{
    extern __shared__ char smc[];
    const uint32_t sb = smem_u32(smc);
    const int tid = threadIdx.x;
    const int lane = tid & 31;
    const int wid = tid >> 5;
    const int g = lane >> 2, t4 = lane & 3;
    const int wm = wid & 3, wn = wid >> 2;

    const uint32_t aBase = (uint32_t)(wm * 32 + (lane & 15)) * 80 + (lane >> 4) * 16;
    const uint32_t bBase = (uint32_t)(wn * 64 + (lane & 7) + ((lane >> 4) << 3)) * 80
                           + ((lane >> 3) & 1) * 16;
    const int lr = tid >> 1, lq = tid & 1;
    const uint32_t ldB = lr * 80 + lq * 32;

    for (int u = blockIdx.x; u < PROJ_UNITS; u += gridDim.x) {
        const int z = u >> 8;
        const int rem = u & 255;
        const int m0 = (rem >> 3) * 128;
        const int n0 = (rem & 7) * 128;

        const float* A;
        __half *Ch, *Cl;
        if (z == 0)      { A = qi; Ch = g_Qh; Cl = g_Ql; }
        else if (z == 1) { A = ki; Ch = g_Kh; Cl = g_Kl; }
        else             { A = vi; Ch = g_Vh; Cl = 0; }
        const size_t woff = (size_t)z * DMODEL * DMODEL;
        const char* BhG = (const char*)(g_WT_hi + woff);
        const char* BlG = (const char*)(g_WT_lo + woff);
        const size_t aRow = (size_t)(m0 + lr) * DMODEL;
        const size_t bRowB = (size_t)(n0 + lr) * DMODEL * 2;

        __syncthreads();   // smem reuse guard across units

        float c[2][8][4];
#pragma unroll
        for (int mb = 0; mb < 2; mb++)
#pragma unroll
            for (int j = 0; j < 8; j++)
#pragma unroll
                for (int i = 0; i < 4; i++) c[mb][j][i] = 0.0f;

        // prologue
        float4 aCur[4], aNext[4];
#pragma unroll
        for (int i = 0; i < 4; i++)
            aCur[i] = ((const float4*)(A + aRow + lq * 16))[i];
#pragma unroll
        for (int j = 0; j < 2; j++) {
            cpa16(sb + 20480 + ldB + j * 16, BhG + bRowB + lq * 32 + j * 16);
            if (z < 2)
                cpa16(sb + 30720 + ldB + j * 16, BlG + bRowB + lq * 32 + j * 16);
        }
        CP_COMMIT();

        for (int kb = 0; kb < 32; kb++) {
            const uint32_t stg = (uint32_t)(kb & 1) * PSTG;
            // convert + store current A chunk (fp16 split)
            {
                uint32_t hb[8], lb[8];
#pragma unroll
                for (int i = 0; i < 4; i++) {
                    split2h(aCur[i].x, aCur[i].y, hb[2 * i], lb[2 * i]);
                    split2h(aCur[i].z, aCur[i].w, hb[2 * i + 1], lb[2 * i + 1]);
                }
                char* dh = smc + stg + ldB;
                char* dl = smc + stg + 10240 + ldB;
                ((uint4*)dh)[0] = make_uint4(hb[0], hb[1], hb[2], hb[3]);
                ((uint4*)dh)[1] = make_uint4(hb[4], hb[5], hb[6], hb[7]);
                ((uint4*)dl)[0] = make_uint4(lb[0], lb[1], lb[2], lb[3]);
                ((uint4*)dl)[1] = make_uint4(lb[4], lb[5], lb[6], lb[7]);
            }
            if (kb + 1 < 32) {
                const uint32_t ns = (uint32_t)((kb + 1) & 1) * PSTG;
                const int ko = (kb + 1) * 32;
#pragma unroll
                for (int i = 0; i < 4; i++)
                    aNext[i] = ((const float4*)(A + aRow + ko + lq * 16))[i];
#pragma unroll
                for (int j = 0; j < 2; j++) {
                    cpa16(sb + ns + 20480 + ldB + j * 16, BhG + bRowB + ko * 2 + lq * 32 + j * 16);
                    if (z < 2)
                        cpa16(sb + ns + 30720 + ldB + j * 16, BlG + bRowB + ko * 2 + lq * 32 + j * 16);
                }
                CP_COMMIT();
                CP_WAIT1();
            } else {
                CP_WAIT0();
            }
            __syncthreads();

#pragma unroll
            for (int c2 = 0; c2 < 2; c2++) {
                uint32_t ah[2][4], al[2][4];
#pragma unroll
                for (int mb = 0; mb < 2; mb++) {
                    ldm_x4(sb + stg + aBase + mb * 1280 + c2 * 32, ah[mb]);
                    ldm_x4(sb + stg + 10240 + aBase + mb * 1280 + c2 * 32, al[mb]);
                }
#pragma unroll
                for (int jj = 0; jj < 4; jj++) {
                    uint32_t r4[4];
                    ldm_x4(sb + stg + 20480 + bBase + jj * 1280 + c2 * 32, r4);
#pragma unroll
                    for (int mb = 0; mb < 2; mb++) {
                        mma_f16(c[mb][2 * jj], ah[mb], r4[0], r4[1]);
                        mma_f16(c[mb][2 * jj + 1], ah[mb], r4[2], r4[3]);
                        mma_f16(c[mb][2 * jj], al[mb], r4[0], r4[1]);
                        mma_f16(c[mb][2 * jj + 1], al[mb], r4[2], r4[3]);
                    }
                }
                if (z < 2) {
#pragma unroll
                    for (int jj = 0; jj < 4; jj++) {
                        uint32_t r4[4];
                        ldm_x4(sb + stg + 30720 + bBase + jj * 1280 + c2 * 32, r4);
#pragma unroll
                        for (int mb = 0; mb < 2; mb++) {
                            mma_f16(c[mb][2 * jj], ah[mb], r4[0], r4[1]);
                            mma_f16(c[mb][2 * jj + 1], ah[mb], r4[2], r4[3]);
                        }
                    }
                }
            }
            __syncthreads();
#pragma unroll
            for (int i = 0; i < 4; i++) aCur[i] = aNext[i];
        }

        // epilogue
#pragma unroll
        for (int mb = 0; mb < 2; mb++) {
#pragma unroll
            for (int j = 0; j < 8; j++) {
                const int R0 = m0 + wm * 32 + mb * 16 + g;
                const int col = n0 + wn * 64 + 8 * j + 2 * t4;
                if (z < 2) {
                    uint32_t hi, lo;
                    split2h(c[mb][j][0], c[mb][j][1], hi, lo);
                    *(uint32_t*)(Ch + (size_t)R0 * DMODEL + col) = hi;
                    *(uint32_t*)(Cl + (size_t)R0 * DMODEL + col) = lo;
                    split2h(c[mb][j][2], c[mb][j][3], hi, lo);
                    *(uint32_t*)(Ch + (size_t)(R0 + 8) * DMODEL + col) = hi;
                    *(uint32_t*)(Cl + (size_t)(R0 + 8) * DMODEL + col) = lo;
                } else {
                    *(uint32_t*)(Ch + (size_t)R0 * DMODEL + col) =
                        pack_h2(c[mb][j][0], c[mb][j][1]);
                    *(uint32_t*)(Ch + (size_t)(R0 + 8) * DMODEL + col) =
                        pack_h2(c[mb][j][2], c[mb][j][3]);
                }
            }
        }
    }
}

// ===========================================================================
// Flash attention, persistent (148 CTAs, 512 units), register-resident,
// fp16 mma: S 3-term, PV single-term (P and V single fp16 plane).
// smem: QH 0, QL 18432; KV stage s at 36864 + s*55296: {KH +0, KL +18432, VH +36864}
// Total 147456 B.
// ===========================================================================
#define KVB  36864
#define KVST 55296
#define ATTN_SMEM 147456
#define ATTN_GRID 148
#define ATTN_UNITS 512

__global__ __launch_bounds__(256, 1) void attn_mma(float* __restrict__ out)
{
    extern __shared__ char smc[];
    const uint32_t sb = smem_u32(smc);
    const int tid = threadIdx.x;
    const int lane = tid & 31;
    const int w = tid >> 5;
    const int g = lane >> 2, t4 = lane & 3;
    const int lr = tid >> 1, lq = tid & 1;
    const uint32_t ldKV = lr * 144 + lq * 64;

    const uint32_t qBase = (uint32_t)(16 * w + (lane & 15)) * 144 + (lane >> 4) * 16;
    const uint32_t kBase = (uint32_t)((lane & 7) + ((lane >> 4) << 3)) * 144
                           + ((lane >> 3) & 1) * 16;
    const uint32_t vBase = (uint32_t)((lane & 7) + (((lane >> 3) & 1) << 3)) * 144
                           + (lane >> 4) * 16;

    for (int u = blockIdx.x; u < ATTN_UNITS; u += gridDim.x) {
        const int b = u >> 8;
        const int h = (u >> 4) & 15;
        const int q0 = (u & 15) * 128;
        const int hoff = h * HDIM;

        __syncthreads();   // smem reuse guard across units

        // prologue: Q (2 planes) + KV tile 0 via cp.async (one group)
        {
            const size_t gQ = ((size_t)(b * SEQ + q0 + lr) * DMODEL + hoff) * 2 + lq * 64;
            const size_t gB = ((size_t)(b * SEQ + lr) * DMODEL + hoff) * 2 + lq * 64;
            const uint32_t dQ = sb + ldKV;
            const uint32_t dKV = sb + KVB + ldKV;
#pragma unroll
            for (int i = 0; i < 4; i++) {
                cpa16(dQ + i * 16,          (const char*)g_Qh + gQ + i * 16);
                cpa16(dQ + 18432 + i * 16,  (const char*)g_Ql + gQ + i * 16);
                cpa16(dKV + i * 16,         (const char*)g_Kh + gB + i * 16);
                cpa16(dKV + 18432 + i * 16, (const char*)g_Kl + gB + i * 16);
                cpa16(dKV + 36864 + i * 16, (const char*)g_Vh + gB + i * 16);
            }
            CP_COMMIT();
        }

        float m0 = -1e30f, m1 = -1e30f, l0 = 0.0f, l1 = 0.0f;
        float O[8][4];
#pragma unroll
        for (int j = 0; j < 8; j++)
#pragma unroll
            for (int i = 0; i < 4; i++) O[j][i] = 0.0f;

        uint32_t aqh[4][4], aql[4][4];

        for (int kt = 0; kt < SEQ / 128; kt++) {
            const uint32_t kv = sb + KVB + (uint32_t)(kt & 1) * KVST;

            if (kt + 1 < SEQ / 128) {
                const size_t gB = ((size_t)(b * SEQ + (kt + 1) * 128 + lr) * DMODEL + hoff) * 2 + lq * 64;
                const uint32_t d = sb + KVB + (uint32_t)((kt + 1) & 1) * KVST + ldKV;
#pragma unroll
                for (int i = 0; i < 4; i++) {
                    cpa16(d + i * 16,         (const char*)g_Kh + gB + i * 16);
                    cpa16(d + 18432 + i * 16, (const char*)g_Kl + gB + i * 16);
                    cpa16(d + 36864 + i * 16, (const char*)g_Vh + gB + i * 16);
                }
                CP_COMMIT();
                CP_WAIT1();
            } else {
                CP_WAIT0();
            }
            __syncthreads();

            if (kt == 0) {
#pragma unroll
                for (int c = 0; c < 4; c++) {
                    ldm_x4(sb + qBase + c * 32, aqh[c]);
                    ldm_x4(sb + 18432 + qBase + c * 32, aql[c]);
                }
            }

            // ---- S = Q K^T (raw), fp16 3-term, merged passes ----
            float S[16][4];
#pragma unroll
            for (int j = 0; j < 16; j++)
#pragma unroll
                for (int i = 0; i < 4; i++) S[j][i] = 0.0f;

#pragma unroll
            for (int c = 0; c < 4; c++) {
#pragma unroll
                for (int jj = 0; jj < 8; jj++) {
                    uint32_t kh[4], kl[4];
                    ldm_x4(kv + kBase + jj * 2304 + c * 32, kh);
                    ldm_x4(kv + 18432 + kBase + jj * 2304 + c * 32, kl);
                    mma_f16(S[2 * jj], aqh[c], kh[0], kh[1]);
                    mma_f16(S[2 * jj + 1], aqh[c], kh[2], kh[3]);
                    mma_f16(S[2 * jj], aql[c], kh[0], kh[1]);
                    mma_f16(S[2 * jj + 1], aql[c], kh[2], kh[3]);
                    mma_f16(S[2 * jj], aqh[c], kl[0], kl[1]);
                    mma_f16(S[2 * jj + 1], aqh[c], kl[2], kl[3]);
                }
            }

            // ---- online softmax in registers ----
            float mx0 = -1e30f, mx1 = -1e30f;
#pragma unroll
            for (int j = 0; j < 16; j++) {
                mx0 = fmaxf(mx0, fmaxf(S[j][0], S[j][1]));
                mx1 = fmaxf(mx1, fmaxf(S[j][2], S[j][3]));
            }
            mx0 = fmaxf(mx0, __shfl_xor_sync(0xffffffffu, mx0, 1));
            mx0 = fmaxf(mx0, __shfl_xor_sync(0xffffffffu, mx0, 2));
            mx1 = fmaxf(mx1, __shfl_xor_sync(0xffffffffu, mx1, 1));
            mx1 = fmaxf(mx1, __shfl_xor_sync(0xffffffffu, mx1, 2));
            const float mn0 = fmaxf(m0, mx0), mn1 = fmaxf(m1, mx1);
            const float al0 = ex2((m0 - mn0) * CEXP);
            const float al1 = ex2((m1 - mn1) * CEXP);
            m0 = mn0; m1 = mn1;

            float s0 = 0.0f, s1 = 0.0f;
#pragma unroll
            for (int j = 0; j < 16; j++) {
                S[j][0] = ex2((S[j][0] - m0) * CEXP);
                S[j][1] = ex2((S[j][1] - m0) * CEXP);
                S[j][2] = ex2((S[j][2] - m1) * CEXP);
                S[j][3] = ex2((S[j][3] - m1) * CEXP);
                s0 += S[j][0] + S[j][1];
                s1 += S[j][2] + S[j][3];
            }
            s0 += __shfl_xor_sync(0xffffffffu, s0, 1);
            s0 += __shfl_xor_sync(0xffffffffu, s0, 2);
            s1 += __shfl_xor_sync(0xffffffffu, s1, 1);
            s1 += __shfl_xor_sync(0xffffffffu, s1, 2);
            l0 = l0 * al0 + s0;
            l1 = l1 * al1 + s1;

#pragma unroll
            for (int j = 0; j < 8; j++) {
                O[j][0] *= al0; O[j][1] *= al0;
                O[j][2] *= al1; O[j][3] *= al1;
            }

            // ---- O += P V  (single fp16 plane each side) ----
#pragma unroll
            for (int c = 0; c < 8; c++) {
                uint32_t ph[4];
                ph[0] = pack_h2(S[2 * c][0], S[2 * c][1]);
                ph[1] = pack_h2(S[2 * c][2], S[2 * c][3]);
                ph[2] = pack_h2(S[2 * c + 1][0], S[2 * c + 1][1]);
                ph[3] = pack_h2(S[2 * c + 1][2], S[2 * c + 1][3]);
#pragma unroll
                for (int jj = 0; jj < 4; jj++) {
                    uint32_t r4[4];
                    ldm_x4t(kv + 36864 + vBase + c * 2304 + jj * 32, r4);
                    mma_f16(O[2 * jj], ph, r4[0], r4[1]);
                    mma_f16(O[2 * jj + 1], ph, r4[2], r4[3]);
                }
            }
            __syncthreads();
        }

        // ---- epilogue ----
        const float i0 = 1.0f / l0;
        const float i1 = 1.0f / l1;
        const size_t R0 = (size_t)(b * SEQ + q0 + 16 * w + g);
#pragma unroll
        for (int j = 0; j < 8; j++) {
            const int col = hoff + 8 * j + 2 * t4;
            *(float2*)&out[R0 * DMODEL + col] = make_float2(O[j][0] * i0, O[j][1] * i0);
            *(float2*)&out[(R0 + 8) * DMODEL + col] = make_float2(O[j][2] * i1, O[j][3] * i1);
        }
    }
}

// ===========================================================================
// kernel_launch
// ===========================================================================
extern "C" void kernel_launch(void* const* d_in, const int* in_sizes, int n_in,
                              void* d_out, int out_size)
{
    const float* q  = (const float*)d_in[0];
    const float* k  = (const float*)d_in[1];
    const float* v  = (const float*)d_in[2];
    const float* Wq = (const float*)d_in[3];
    const float* Wk = (const float*)d_in[4];
    const float* Wv = (const float*)d_in[5];
    float* out = (float*)d_out;

    wt_convert<<<dim3(32, 32, 3), dim3(32, 8)>>>(Wq, Wk, Wv);

    cudaFuncSetAttribute(proj_mma, cudaFuncAttributeMaxDynamicSharedMemorySize, PROJ_SMEM);
    proj_mma<<<PROJ_GRID, 256, PROJ_SMEM>>>(q, k, v);

    cudaFuncSetAttribute(attn_mma, cudaFuncAttributeMaxDynamicSharedMemorySize, ATTN_SMEM);
    attn_mma<<<ATTN_GRID, 256, ATTN_SMEM>>>(out);
}